// round 9
// baseline (speedup 1.0000x reference)
#include <cuda_runtime.h>
#include <cstdint>
#include <math.h>

// NeuralODE via mma.sync m16n8k8 tf32, cp.async pipeline, fragment-native layouts.
// h_{n+1} = h_n + 0.1 * tanh(h_n @ W[k]^T + b[k]), k = n/10, n = 0..99, B=D=1024.
// R9: two independent 8-warp pipeline groups per CTA (512 threads). Group g
// handles K-stages s == g (mod 2) with group-local named barriers (bar.sync
// id,256) -- no block-wide sync in the mainloop. K-partials merged at the end
// via the k-split exchange. Warp tile 32x32 (4m x 2n per group), CTA 128x64.

#define D_DIM   1024
#define BM      128
#define BN      64
#define BK      64
#define THREADS 512
#define KITERS  16
#define STAGES  4

#define A_WORDS 8192                 // 128 rows x 64 k
#define B_WORDS 4096                 // 64 n x 64 k
#define STAGE_WORDS (A_WORDS + B_WORDS)   // 12288
#define SMEM_BYTES (STAGES * STAGE_WORDS * 4)  // 196608

__device__ uint32_t g_Wtf[10u * 1024u * 1024u];   // W tf32, B-block layout
__device__ uint32_t g_Htf[2][1024u * 1024u];      // H tf32 ping-pong, A-block layout

__device__ __forceinline__ uint32_t f2tf32(float f) {
    uint32_t r;
    asm("cvt.rna.tf32.f32 %0, %1;" : "=r"(r) : "f"(f));
    return r;
}

__device__ __forceinline__ void mma_tf32(float c[4],
                                         uint32_t a0, uint32_t a1,
                                         uint32_t a2, uint32_t a3,
                                         uint32_t b0, uint32_t b1) {
    asm volatile(
        "mma.sync.aligned.m16n8k8.row.col.f32.tf32.tf32.f32 "
        "{%0,%1,%2,%3}, {%4,%5,%6,%7}, {%8,%9}, {%0,%1,%2,%3};"
        : "+f"(c[0]), "+f"(c[1]), "+f"(c[2]), "+f"(c[3])
        : "r"(a0), "r"(a1), "r"(a2), "r"(a3), "r"(b0), "r"(b1));
}

__device__ __forceinline__ float fast_tanh(float x) {
    float ax = fabsf(x);
    float t = __expf(-2.0f * ax);
    float r = __fdividef(1.0f - t, 1.0f + t);
    return copysignf(r, x);
}

__device__ __forceinline__ uint32_t smem_u32(const void* p) {
    uint32_t a;
    asm("{ .reg .u64 t; cvta.to.shared.u64 t, %1; cvt.u32.u64 %0, t; }"
        : "=r"(a) : "l"(p));
    return a;
}

#define CP_ASYNC(dst, src) \
    asm volatile("cp.async.cg.shared.global [%0], [%1], 16;" \
                 :: "r"(dst), "l"(src) : "memory")
#define CP_COMMIT() asm volatile("cp.async.commit_group;" ::: "memory")
#define CP_WAIT1()  asm volatile("cp.async.wait_group 1;" ::: "memory")
#define GROUP_BAR(id) \
    asm volatile("bar.sync %0, 256;" :: "r"(id) : "memory")

// ---- converts into fragment-block layouts (verified R7/R8) ----
__global__ void convert_W(const float* __restrict__ W, uint32_t* __restrict__ out)
{
    const size_t npairs = 10ull * 1024 * 1024 / 2;
    for (size_t p = (size_t)blockIdx.x * blockDim.x + threadIdx.x; p < npairs;
         p += (size_t)gridDim.x * blockDim.x) {
        uint32_t blk  = (uint32_t)(p >> 5);
        uint32_t lane = (uint32_t)(p & 31);
        uint32_t slab = blk >> 14;
        uint32_t b2   = blk & 16383u;
        uint32_t nb = b2 >> 7, kb = b2 & 127u;
        uint32_t g = lane >> 2, tig = lane & 3;
        const float* src = W + (size_t)slab * 1048576u
                             + (size_t)(nb * 8 + g) * 1024u + kb * 8 + tig;
        uint2 v;
        v.x = f2tf32(src[0]);
        v.y = f2tf32(src[4]);
        *reinterpret_cast<uint2*>(out + p * 2) = v;
    }
}

__global__ void convert_X(const float* __restrict__ x, uint32_t* __restrict__ out)
{
    const int nquads = 1024 * 1024 / 4;
    for (int q = blockIdx.x * blockDim.x + threadIdx.x; q < nquads;
         q += gridDim.x * blockDim.x) {
        uint32_t blk  = (uint32_t)q >> 5;
        uint32_t lane = (uint32_t)q & 31;
        uint32_t rb = blk >> 7, kb = blk & 127u;
        uint32_t g = lane >> 2, tig = lane & 3;
        const float* s0 = x + (size_t)(rb * 16 + g) * 1024u + kb * 8 + tig;
        uint4 v;
        v.x = f2tf32(s0[0]);
        v.y = f2tf32(s0[8192]);
        v.z = f2tf32(s0[4]);
        v.w = f2tf32(s0[8192 + 4]);
        *reinterpret_cast<uint4*>(out + (size_t)q * 4) = v;
    }
}

__global__ __launch_bounds__(THREADS, 1)
void ode_step(const uint32_t* __restrict__ Atf,   // H tf32, A-block layout
              const uint32_t* __restrict__ Btf,   // W slab tf32, B-block layout
              const float*    __restrict__ Hfp,   // traj[n] fp32 row-major
              const float*    __restrict__ bk,
              float*          __restrict__ Hout,  // traj[n+1] fp32 row-major
              uint32_t*       __restrict__ Houttf)// next H tf32, A-block layout
{
    extern __shared__ uint32_t smem[];
    const uint32_t sbase = smem_u32(smem);

    const int tid  = threadIdx.x;
    const int wid  = tid >> 5;
    const int lane = tid & 31;
    const int g    = lane >> 2;
    const int tig  = lane & 3;
    const int grp  = wid >> 3;       // pipeline group 0/1 (also k-split id)
    const int gtid = tid & 255;      // thread id within group
    const int gw   = wid & 7;        // warp id within group
    const int wm   = gw & 3;         // 4 warp rows of 32
    const int wn   = gw >> 2;        // 2 warp cols of 32
    const int bm   = blockIdx.y * BM;
    const int bn   = blockIdx.x * BN;
    const int rb0  = blockIdx.y * 8;  // A 16-row block base
    const int nb0  = blockIdx.x * 8;  // B 8-col block base
    const int barid = grp + 1;

    // issue one K-stage's loads using this group's 256 threads
    auto issue_stage = [&](int s) {
        const int slot = s & (STAGES - 1);
        const uint32_t sst = sbase + (uint32_t)(slot * STAGE_WORDS) * 4u;
        const int kb0 = s * 8;
#pragma unroll
        for (int i = 0; i < 8; i++) {           // A: 2048 16B chunks / 256 thr
            int c = gtid + i * 256;
            int rbl = c >> 8, j = c & 255;
            const uint32_t* src = Atf + ((size_t)(rb0 + rbl) * 128 + kb0) * 128 + j * 4;
            CP_ASYNC(sst + (uint32_t)(rbl * 1024 + j * 4) * 4u, src);
        }
#pragma unroll
        for (int i = 0; i < 4; i++) {           // B: 1024 16B chunks / 256 thr
            int c = gtid + i * 256;
            int nbl = c >> 7, j = c & 127;
            const uint32_t* src = Btf + ((size_t)(nb0 + nbl) * 128 + kb0) * 64 + j * 4;
            CP_ASYNC(sst + (uint32_t)(A_WORDS + nbl * 512 + j * 4) * 4u, src);
        }
        CP_COMMIT();
    };

    float acc[2][4][4];     // mt 0..1 (16 rows), nt 0..3 (8 cols)
#pragma unroll
    for (int mt = 0; mt < 2; mt++)
#pragma unroll
        for (int nt = 0; nt < 4; nt++)
#pragma unroll
            for (int r = 0; r < 4; r++) acc[mt][nt][r] = 0.0f;

    uint32_t fa[2][2][4], fb[2][4][2];

    auto load_frag = [&](const uint32_t* __restrict__ st, int j, int p) {
#pragma unroll
        for (int mt = 0; mt < 2; mt++) {
            uint4 v = *reinterpret_cast<const uint4*>(
                st + ((wm * 2 + mt) * 8 + j) * 128 + lane * 4);
            fa[p][mt][0] = v.x; fa[p][mt][1] = v.y;
            fa[p][mt][2] = v.z; fa[p][mt][3] = v.w;
        }
#pragma unroll
        for (int nt = 0; nt < 4; nt++) {
            uint2 v = *reinterpret_cast<const uint2*>(
                st + A_WORDS + ((wn * 4 + nt) * 8 + j) * 64 + lane * 2);
            fb[p][nt][0] = v.x; fb[p][nt][1] = v.y;
        }
    };

    auto do_mma = [&](int p) {
#pragma unroll
        for (int mt = 0; mt < 2; mt++)
#pragma unroll
            for (int nt = 0; nt < 4; nt++)
                mma_tf32(acc[mt][nt],
                         fa[p][mt][0], fa[p][mt][1], fa[p][mt][2], fa[p][mt][3],
                         fb[p][nt][0], fb[p][nt][1]);
    };

    // ---- group-local pipeline: group grp owns stages grp, grp+2, ..., grp+14 ----
    issue_stage(grp);
    issue_stage(grp + 2);

    for (int t = grp; t < KITERS; t += 2) {
        CP_WAIT1();          // own stage t landed (t+2 may be pending)
        GROUP_BAR(barid);    // group-wide visibility of stage t

        const uint32_t* st = smem + (t & (STAGES - 1)) * STAGE_WORDS;
        load_frag(st, 0, 0);
#pragma unroll
        for (int j = 0; j < 8; j++) {
            if (j < 7) load_frag(st, j + 1, (j + 1) & 1);
            do_mma(j & 1);
        }

        GROUP_BAR(barid);    // all group warps done reading slot before refill
        if (t + 4 < KITERS) issue_stage(t + 4);
        else CP_COMMIT();    // empty group keeps wait_group counting exact
    }

    // ---- k-split reduction between the two groups ----
    __syncthreads();
    float* ex = reinterpret_cast<float*>(smem);
    const int p = gw;              // (wm, wn) pair id, 0..7 (same map both groups)
    if (grp == 0) {
        // group0 gives away nt 2..3
#pragma unroll
        for (int mt = 0; mt < 2; mt++)
#pragma unroll
            for (int nh = 0; nh < 2; nh++) {
                int q = mt * 2 + nh;
                float4 v = { acc[mt][2 + nh][0], acc[mt][2 + nh][1],
                             acc[mt][2 + nh][2], acc[mt][2 + nh][3] };
                *reinterpret_cast<float4*>(ex + (p * 4 + q) * 128 + lane * 4) = v;
            }
    } else {
        // group1 gives away nt 0..1
#pragma unroll
        for (int mt = 0; mt < 2; mt++)
#pragma unroll
            for (int nh = 0; nh < 2; nh++) {
                int q = mt * 2 + nh;
                float4 v = { acc[mt][nh][0], acc[mt][nh][1],
                             acc[mt][nh][2], acc[mt][nh][3] };
                *reinterpret_cast<float4*>(ex + 4096 + (p * 4 + q) * 128 + lane * 4) = v;
            }
    }
    __syncthreads();
    const int ntb = grp ? 2 : 0;     // nt range this warp epilogues
    const int exo = grp ? 0 : 4096;  // partner's region
#pragma unroll
    for (int mt = 0; mt < 2; mt++)
#pragma unroll
        for (int nh = 0; nh < 2; nh++) {
            int q = mt * 2 + nh;
            float4 v = *reinterpret_cast<const float4*>(
                ex + exo + (p * 4 + q) * 128 + lane * 4);
            acc[mt][ntb + nh][0] += v.x;
            acc[mt][ntb + nh][1] += v.y;
            acc[mt][ntb + nh][2] += v.z;
            acc[mt][ntb + nh][3] += v.w;
        }

    // ---- fused epilogue over this warp's half (nt = ntb..ntb+1) ----
#pragma unroll
    for (int mt = 0; mt < 2; mt++) {
#pragma unroll
        for (int nh = 0; nh < 2; nh++) {
            const int nt = ntb + nh;
            const int R = bm + wm * 32 + mt * 16 + g;
            const int C = bn + wn * 32 + nt * 8 + tig * 2;
            const float b0 = __ldg(&bk[C]);
            const float b1 = __ldg(&bk[C + 1]);

            float2 h0 = *reinterpret_cast<const float2*>(&Hfp[(size_t)R * D_DIM + C]);
            float2 h1 = *reinterpret_cast<const float2*>(&Hfp[(size_t)(R + 8) * D_DIM + C]);
            float o0 = h0.x + 0.1f * fast_tanh(acc[mt][nt][0] + b0);
            float o1 = h0.y + 0.1f * fast_tanh(acc[mt][nt][1] + b1);
            float o2 = h1.x + 0.1f * fast_tanh(acc[mt][nt][2] + b0);
            float o3 = h1.y + 0.1f * fast_tanh(acc[mt][nt][3] + b1);
            *reinterpret_cast<float2*>(&Hout[(size_t)R * D_DIM + C]) = make_float2(o0, o1);
            *reinterpret_cast<float2*>(&Hout[(size_t)(R + 8) * D_DIM + C]) = make_float2(o2, o3);

            // scatter tf32 into next-step A-block layout (verified R7/R8)
            const int rb = R >> 4, kb = C >> 3;
            const int t2 = tig * 2;
            const int kw = t2 >> 2;
            const int lane0 = g * 4 + (t2 & 3);
            const int lane1 = g * 4 + ((t2 + 1) & 3);
            uint32_t* base = Houttf + ((size_t)rb * 128 + kb) * 128 + 2 * kw;
            uint2 u02 = { f2tf32(o0), f2tf32(o2) };
            uint2 u13 = { f2tf32(o1), f2tf32(o3) };
            *reinterpret_cast<uint2*>(base + lane0 * 4) = u02;
            *reinterpret_cast<uint2*>(base + lane1 * 4) = u13;
        }
    }
}

extern "C" void kernel_launch(void* const* d_in, const int* in_sizes, int n_in,
                              void* d_out, int out_size)
{
    (void)in_sizes; (void)n_in; (void)out_size;
    const float* x = (const float*)d_in[0];   // [1024, 1024]
    const float* W = (const float*)d_in[1];   // [10, 1024, 1024]
    const float* b = (const float*)d_in[2];   // [10, 1024]

    float* out  = (float*)d_out;
    const size_t BD = (size_t)D_DIM * D_DIM;
    float* feat = out;
    float* traj = out + BD;

    uint32_t *wtf = nullptr, *htf = nullptr;
    cudaGetSymbolAddress((void**)&wtf, g_Wtf);
    cudaGetSymbolAddress((void**)&htf, g_Htf);
    uint32_t* htf0 = htf;
    uint32_t* htf1 = htf + BD;

    cudaFuncSetAttribute(ode_step,
                         cudaFuncAttributeMaxDynamicSharedMemorySize, SMEM_BYTES);

    convert_W<<<4096, 256>>>(W, wtf);
    convert_X<<<1024, 256>>>(x, htf0);
    cudaMemcpyAsync(traj, x, BD * sizeof(float), cudaMemcpyDeviceToDevice, 0);

    dim3 grid(D_DIM / BN, D_DIM / BM);   // (16, 8) = 128 CTAs
    dim3 block(THREADS);

    for (int n = 0; n < 100; n++) {
        int k = n / 10;
        uint32_t* hin  = (n & 1) ? htf1 : htf0;
        uint32_t* hnew = (n & 1) ? htf0 : htf1;
        ode_step<<<grid, block, SMEM_BYTES, 0>>>(
            hin,
            wtf + (size_t)k * BD,
            traj + (size_t)n * BD,
            b + (size_t)k * D_DIM,
            traj + (size_t)(n + 1) * BD,
            hnew);
    }

    cudaMemcpyAsync(feat, traj + (size_t)100 * BD, BD * sizeof(float),
                    cudaMemcpyDeviceToDevice, 0);
}

// round 10
// speedup vs baseline: 1.2030x; 1.2030x over previous
#include <cuda_runtime.h>
#include <cstdint>
#include <math.h>

// NeuralODE via mma.sync m16n8k8 tf32, cp.async pipeline, fragment-native layouts.
// h_{n+1} = h_n + 0.1 * tanh(h_n @ W[k]^T + b[k]), k = n/10, n = 0..99, B=D=1024.
// R10: CTA tile 64x64, 256 threads (8 warps = 2m x 2n x 2k), 3-stage ring
// (96KB smem) -> 2 CTAs co-resident per SM = two independent pipelines per SM,
// grid (16,16)=256 CTAs covers all 148 SMs. Fragment-block global layouts.

#define D_DIM   1024
#define BM      64
#define BN      64
#define BK      64
#define THREADS 256
#define KITERS  16
#define STAGES  3

#define A_WORDS 4096                 // 64 rows x 64 k
#define B_WORDS 4096                 // 64 n x 64 k
#define STAGE_WORDS (A_WORDS + B_WORDS)   // 8192
#define SMEM_BYTES (STAGES * STAGE_WORDS * 4)  // 98304

__device__ uint32_t g_Wtf[10u * 1024u * 1024u];   // W tf32, B-block layout
__device__ uint32_t g_Htf[2][1024u * 1024u];      // H tf32 ping-pong, A-block layout

__device__ __forceinline__ uint32_t f2tf32(float f) {
    uint32_t r;
    asm("cvt.rna.tf32.f32 %0, %1;" : "=r"(r) : "f"(f));
    return r;
}

__device__ __forceinline__ void mma_tf32(float c[4],
                                         uint32_t a0, uint32_t a1,
                                         uint32_t a2, uint32_t a3,
                                         uint32_t b0, uint32_t b1) {
    asm volatile(
        "mma.sync.aligned.m16n8k8.row.col.f32.tf32.tf32.f32 "
        "{%0,%1,%2,%3}, {%4,%5,%6,%7}, {%8,%9}, {%0,%1,%2,%3};"
        : "+f"(c[0]), "+f"(c[1]), "+f"(c[2]), "+f"(c[3])
        : "r"(a0), "r"(a1), "r"(a2), "r"(a3), "r"(b0), "r"(b1));
}

__device__ __forceinline__ float fast_tanh(float x) {
    float ax = fabsf(x);
    float t = __expf(-2.0f * ax);
    float r = __fdividef(1.0f - t, 1.0f + t);
    return copysignf(r, x);
}

__device__ __forceinline__ uint32_t smem_u32(const void* p) {
    uint32_t a;
    asm("{ .reg .u64 t; cvta.to.shared.u64 t, %1; cvt.u32.u64 %0, t; }"
        : "=r"(a) : "l"(p));
    return a;
}

#define CP_ASYNC(dst, src) \
    asm volatile("cp.async.cg.shared.global [%0], [%1], 16;" \
                 :: "r"(dst), "l"(src) : "memory")
#define CP_COMMIT() asm volatile("cp.async.commit_group;" ::: "memory")
#define CP_WAIT1()  asm volatile("cp.async.wait_group 1;" ::: "memory")

// ---- converts into fragment-block layouts (verified R7/R8) ----
__global__ void convert_W(const float* __restrict__ W, uint32_t* __restrict__ out)
{
    const size_t npairs = 10ull * 1024 * 1024 / 2;
    for (size_t p = (size_t)blockIdx.x * blockDim.x + threadIdx.x; p < npairs;
         p += (size_t)gridDim.x * blockDim.x) {
        uint32_t blk  = (uint32_t)(p >> 5);
        uint32_t lane = (uint32_t)(p & 31);
        uint32_t slab = blk >> 14;
        uint32_t b2   = blk & 16383u;
        uint32_t nb = b2 >> 7, kb = b2 & 127u;
        uint32_t g = lane >> 2, tig = lane & 3;
        const float* src = W + (size_t)slab * 1048576u
                             + (size_t)(nb * 8 + g) * 1024u + kb * 8 + tig;
        uint2 v;
        v.x = f2tf32(src[0]);
        v.y = f2tf32(src[4]);
        *reinterpret_cast<uint2*>(out + p * 2) = v;
    }
}

__global__ void convert_X(const float* __restrict__ x, uint32_t* __restrict__ out)
{
    const int nquads = 1024 * 1024 / 4;
    for (int q = blockIdx.x * blockDim.x + threadIdx.x; q < nquads;
         q += gridDim.x * blockDim.x) {
        uint32_t blk  = (uint32_t)q >> 5;
        uint32_t lane = (uint32_t)q & 31;
        uint32_t rb = blk >> 7, kb = blk & 127u;
        uint32_t g = lane >> 2, tig = lane & 3;
        const float* s0 = x + (size_t)(rb * 16 + g) * 1024u + kb * 8 + tig;
        uint4 v;
        v.x = f2tf32(s0[0]);
        v.y = f2tf32(s0[8192]);
        v.z = f2tf32(s0[4]);
        v.w = f2tf32(s0[8192 + 4]);
        *reinterpret_cast<uint4*>(out + (size_t)q * 4) = v;
    }
}

__global__ __launch_bounds__(THREADS, 2)
void ode_step(const uint32_t* __restrict__ Atf,   // H tf32, A-block layout
              const uint32_t* __restrict__ Btf,   // W slab tf32, B-block layout
              const float*    __restrict__ Hfp,   // traj[n] fp32 row-major
              const float*    __restrict__ bk,
              float*          __restrict__ Hout,  // traj[n+1] fp32 row-major
              uint32_t*       __restrict__ Houttf)// next H tf32, A-block layout
{
    extern __shared__ uint32_t smem[];
    const uint32_t sbase = smem_u32(smem);

    const int tid  = threadIdx.x;
    const int wid  = tid >> 5;
    const int lane = tid & 31;
    const int g    = lane >> 2;
    const int tig  = lane & 3;
    const int wm   = wid & 1;        // 2 warp rows of 32
    const int wn   = (wid >> 1) & 1; // 2 warp cols of 32
    const int ks   = wid >> 2;       // k-split half
    const int bm   = blockIdx.y * BM;
    const int bn   = blockIdx.x * BN;
    const int rb0  = blockIdx.y * 4;  // A 16-row block base (4 blocks per CTA)
    const int nb0  = blockIdx.x * 8;  // B 8-col block base

    auto issue_stage = [&](int s, int slot) {
        const uint32_t sst = sbase + (uint32_t)(slot * STAGE_WORDS) * 4u;
        const int kb0 = s * 8;
#pragma unroll
        for (int i = 0; i < 4; i++) {           // A: 1024 16B chunks
            int c = tid + i * THREADS;
            int rbl = c >> 8, j = c & 255;
            const uint32_t* src = Atf + ((size_t)(rb0 + rbl) * 128 + kb0) * 128 + j * 4;
            CP_ASYNC(sst + (uint32_t)(rbl * 1024 + j * 4) * 4u, src);
        }
#pragma unroll
        for (int i = 0; i < 4; i++) {           // B: 1024 16B chunks
            int c = tid + i * THREADS;
            int nbl = c >> 7, j = c & 127;
            const uint32_t* src = Btf + ((size_t)(nb0 + nbl) * 128 + kb0) * 64 + j * 4;
            CP_ASYNC(sst + (uint32_t)(A_WORDS + nbl * 512 + j * 4) * 4u, src);
        }
        CP_COMMIT();
    };

    float acc[2][4][4];     // mt 0..1 (16 rows), nt 0..3 (8 cols)
#pragma unroll
    for (int mt = 0; mt < 2; mt++)
#pragma unroll
        for (int nt = 0; nt < 4; nt++)
#pragma unroll
            for (int r = 0; r < 4; r++) acc[mt][nt][r] = 0.0f;

    uint32_t fa[2][2][4], fb[2][4][2];

    auto load_frag = [&](const uint32_t* __restrict__ st, int j, int p) {
#pragma unroll
        for (int mt = 0; mt < 2; mt++) {
            uint4 v = *reinterpret_cast<const uint4*>(
                st + ((wm * 2 + mt) * 8 + j) * 128 + lane * 4);
            fa[p][mt][0] = v.x; fa[p][mt][1] = v.y;
            fa[p][mt][2] = v.z; fa[p][mt][3] = v.w;
        }
#pragma unroll
        for (int nt = 0; nt < 4; nt++) {
            uint2 v = *reinterpret_cast<const uint2*>(
                st + A_WORDS + ((wn * 4 + nt) * 8 + j) * 64 + lane * 2);
            fb[p][nt][0] = v.x; fb[p][nt][1] = v.y;
        }
    };

    auto do_mma = [&](int p) {
#pragma unroll
        for (int mt = 0; mt < 2; mt++)
#pragma unroll
            for (int nt = 0; nt < 4; nt++)
                mma_tf32(acc[mt][nt],
                         fa[p][mt][0], fa[p][mt][1], fa[p][mt][2], fa[p][mt][3],
                         fb[p][nt][0], fb[p][nt][1]);
    };

    issue_stage(0, 0);
    issue_stage(1, 1);

    const int jb = ks * 4;   // this warp's k8-round base within a stage
    int slot = 0, nslot = 2;
    for (int s = 0; s < KITERS; s++) {
        CP_WAIT1();          // stage s landed (s+1 may be pending)
        __syncthreads();     // all warps: stage s visible AND stage s-1 fully read

        if (s + 2 < KITERS) issue_stage(s + 2, nslot);
        else CP_COMMIT();    // keep wait_group counting exact

        const uint32_t* st = smem + slot * STAGE_WORDS;
        load_frag(st, jb, 0);
#pragma unroll
        for (int jj = 0; jj < 4; jj++) {
            if (jj < 3) load_frag(st, jb + jj + 1, (jj + 1) & 1);
            do_mma(jj & 1);
        }
        slot = slot + 1 == STAGES ? 0 : slot + 1;
        nslot = nslot + 1 == STAGES ? 0 : nslot + 1;
    }

    // ---- k-split reduction: exchange the nt-half each side will NOT epilogue ----
    __syncthreads();
    float* ex = reinterpret_cast<float*>(smem);
    const int p = wid & 3;          // (wm, wn) pair id, 0..3
    if (ks == 0) {
        // ks0 gives away nt 2..3
#pragma unroll
        for (int mt = 0; mt < 2; mt++)
#pragma unroll
            for (int nh = 0; nh < 2; nh++) {
                int q = mt * 2 + nh;
                float4 v = { acc[mt][2 + nh][0], acc[mt][2 + nh][1],
                             acc[mt][2 + nh][2], acc[mt][2 + nh][3] };
                *reinterpret_cast<float4*>(ex + (p * 4 + q) * 128 + lane * 4) = v;
            }
    } else {
        // ks1 gives away nt 0..1
#pragma unroll
        for (int mt = 0; mt < 2; mt++)
#pragma unroll
            for (int nh = 0; nh < 2; nh++) {
                int q = mt * 2 + nh;
                float4 v = { acc[mt][nh][0], acc[mt][nh][1],
                             acc[mt][nh][2], acc[mt][nh][3] };
                *reinterpret_cast<float4*>(ex + 2048 + (p * 4 + q) * 128 + lane * 4) = v;
            }
    }
    __syncthreads();
    const int ntb = ks ? 2 : 0;     // nt range this warp epilogues
    const int exo = ks ? 0 : 2048;  // partner's region
#pragma unroll
    for (int mt = 0; mt < 2; mt++)
#pragma unroll
        for (int nh = 0; nh < 2; nh++) {
            int q = mt * 2 + nh;
            float4 v = *reinterpret_cast<const float4*>(
                ex + exo + (p * 4 + q) * 128 + lane * 4);
            acc[mt][ntb + nh][0] += v.x;
            acc[mt][ntb + nh][1] += v.y;
            acc[mt][ntb + nh][2] += v.z;
            acc[mt][ntb + nh][3] += v.w;
        }

    // ---- fused epilogue over this warp's half (nt = ntb..ntb+1) ----
#pragma unroll
    for (int mt = 0; mt < 2; mt++) {
#pragma unroll
        for (int nh = 0; nh < 2; nh++) {
            const int nt = ntb + nh;
            const int R = bm + wm * 32 + mt * 16 + g;
            const int C = bn + wn * 32 + nt * 8 + tig * 2;
            const float b0 = __ldg(&bk[C]);
            const float b1 = __ldg(&bk[C + 1]);

            float2 h0 = *reinterpret_cast<const float2*>(&Hfp[(size_t)R * D_DIM + C]);
            float2 h1 = *reinterpret_cast<const float2*>(&Hfp[(size_t)(R + 8) * D_DIM + C]);
            float o0 = h0.x + 0.1f * fast_tanh(acc[mt][nt][0] + b0);
            float o1 = h0.y + 0.1f * fast_tanh(acc[mt][nt][1] + b1);
            float o2 = h1.x + 0.1f * fast_tanh(acc[mt][nt][2] + b0);
            float o3 = h1.y + 0.1f * fast_tanh(acc[mt][nt][3] + b1);
            *reinterpret_cast<float2*>(&Hout[(size_t)R * D_DIM + C]) = make_float2(o0, o1);
            *reinterpret_cast<float2*>(&Hout[(size_t)(R + 8) * D_DIM + C]) = make_float2(o2, o3);

            // scatter tf32 into next-step A-block layout (verified R7/R8)
            const int rb = R >> 4, kb = C >> 3;
            const int t2 = tig * 2;
            const int kw = t2 >> 2;
            const int lane0 = g * 4 + (t2 & 3);
            const int lane1 = g * 4 + ((t2 + 1) & 3);
            uint32_t* base = Houttf + ((size_t)rb * 128 + kb) * 128 + 2 * kw;
            uint2 u02 = { f2tf32(o0), f2tf32(o2) };
            uint2 u13 = { f2tf32(o1), f2tf32(o3) };
            *reinterpret_cast<uint2*>(base + lane0 * 4) = u02;
            *reinterpret_cast<uint2*>(base + lane1 * 4) = u13;
        }
    }
}

extern "C" void kernel_launch(void* const* d_in, const int* in_sizes, int n_in,
                              void* d_out, int out_size)
{
    (void)in_sizes; (void)n_in; (void)out_size;
    const float* x = (const float*)d_in[0];   // [1024, 1024]
    const float* W = (const float*)d_in[1];   // [10, 1024, 1024]
    const float* b = (const float*)d_in[2];   // [10, 1024]

    float* out  = (float*)d_out;
    const size_t BD = (size_t)D_DIM * D_DIM;
    float* feat = out;
    float* traj = out + BD;

    uint32_t *wtf = nullptr, *htf = nullptr;
    cudaGetSymbolAddress((void**)&wtf, g_Wtf);
    cudaGetSymbolAddress((void**)&htf, g_Htf);
    uint32_t* htf0 = htf;
    uint32_t* htf1 = htf + BD;

    cudaFuncSetAttribute(ode_step,
                         cudaFuncAttributeMaxDynamicSharedMemorySize, SMEM_BYTES);

    convert_W<<<4096, 256>>>(W, wtf);
    convert_X<<<1024, 256>>>(x, htf0);
    cudaMemcpyAsync(traj, x, BD * sizeof(float), cudaMemcpyDeviceToDevice, 0);

    dim3 grid(D_DIM / BN, D_DIM / BM);   // (16, 16) = 256 CTAs
    dim3 block(THREADS);

    for (int n = 0; n < 100; n++) {
        int k = n / 10;
        uint32_t* hin  = (n & 1) ? htf1 : htf0;
        uint32_t* hnew = (n & 1) ? htf0 : htf1;
        ode_step<<<grid, block, SMEM_BYTES, 0>>>(
            hin,
            wtf + (size_t)k * BD,
            traj + (size_t)n * BD,
            b + (size_t)k * D_DIM,
            traj + (size_t)(n + 1) * BD,
            hnew);
    }

    cudaMemcpyAsync(feat, traj + (size_t)100 * BD, BD * sizeof(float),
                    cudaMemcpyDeviceToDevice, 0);
}

// round 11
// speedup vs baseline: 1.2043x; 1.0011x over previous
#include <cuda_runtime.h>
#include <cstdint>
#include <math.h>

// NeuralODE via mma.sync m16n8k8 tf32, cp.async pipeline, fragment-native layouts.
// h_{n+1} = h_n + 0.1 * tanh(h_n @ W[k]^T + b[k]), k = n/10, n = 0..99, B=D=1024.
// R11: R10 base (CTA 64x64, 256 thr, 2m x 2n x 2k, 3-stage ring, 2 CTAs/SM)
// + k16-fused W layout so B fragments load as LDS.128 covering 2 k8-rounds
// + hand-scheduled stage body (frag LDS first, cp.async burst behind it).

#define D_DIM   1024
#define BM      64
#define BN      64
#define BK      64
#define THREADS 256
#define KITERS  16
#define STAGES  3

#define A_WORDS 4096                 // 64 rows x 64 k
#define B_WORDS 4096                 // 64 n x 64 k
#define STAGE_WORDS (A_WORDS + B_WORDS)   // 8192
#define SMEM_BYTES (STAGES * STAGE_WORDS * 4)  // 98304

__device__ uint32_t g_Wtf[10u * 1024u * 1024u];   // W tf32, k16-fused B-block layout
__device__ uint32_t g_Htf[2][1024u * 1024u];      // H tf32 ping-pong, A-block layout

__device__ __forceinline__ uint32_t f2tf32(float f) {
    uint32_t r;
    asm("cvt.rna.tf32.f32 %0, %1;" : "=r"(r) : "f"(f));
    return r;
}

__device__ __forceinline__ void mma_tf32(float c[4],
                                         uint32_t a0, uint32_t a1,
                                         uint32_t a2, uint32_t a3,
                                         uint32_t b0, uint32_t b1) {
    asm volatile(
        "mma.sync.aligned.m16n8k8.row.col.f32.tf32.tf32.f32 "
        "{%0,%1,%2,%3}, {%4,%5,%6,%7}, {%8,%9}, {%0,%1,%2,%3};"
        : "+f"(c[0]), "+f"(c[1]), "+f"(c[2]), "+f"(c[3])
        : "r"(a0), "r"(a1), "r"(a2), "r"(a3), "r"(b0), "r"(b1));
}

__device__ __forceinline__ float fast_tanh(float x) {
    float ax = fabsf(x);
    float t = __expf(-2.0f * ax);
    float r = __fdividef(1.0f - t, 1.0f + t);
    return copysignf(r, x);
}

__device__ __forceinline__ uint32_t smem_u32(const void* p) {
    uint32_t a;
    asm("{ .reg .u64 t; cvta.to.shared.u64 t, %1; cvt.u32.u64 %0, t; }"
        : "=r"(a) : "l"(p));
    return a;
}

#define CP_ASYNC(dst, src) \
    asm volatile("cp.async.cg.shared.global [%0], [%1], 16;" \
                 :: "r"(dst), "l"(src) : "memory")
#define CP_COMMIT() asm volatile("cp.async.commit_group;" ::: "memory")
#define CP_WAIT1()  asm volatile("cp.async.wait_group 1;" ::: "memory")

// ---- W convert: k16-fused B-block layout ----
// block (slab, nb 0..127, kp 0..63) of 128 words at ((slab*128+nb)*64+kp)*128.
// lane l=(g,tig) quad at lane*4: { W[n][kp*16+tig], W[n][kp*16+tig+4],
//                                  W[n][kp*16+8+tig], W[n][kp*16+12+tig] }
// with n = nb*8+g.  (words 0,1 = k8-round even; words 2,3 = round odd)
__global__ void convert_W(const float* __restrict__ W, uint32_t* __restrict__ out)
{
    const int nquads = 10 * 1024 * 1024 / 4;
    for (int q = blockIdx.x * blockDim.x + threadIdx.x; q < nquads;
         q += gridDim.x * blockDim.x) {
        uint32_t blk  = (uint32_t)q >> 5;
        uint32_t lane = (uint32_t)q & 31;
        uint32_t slab = blk >> 13;          // 8192 blocks per slab
        uint32_t rem  = blk & 8191u;
        uint32_t nb = rem >> 6, kp = rem & 63u;
        uint32_t g = lane >> 2, tig = lane & 3;
        const float* s = W + (size_t)slab * 1048576u
                           + (size_t)(nb * 8 + g) * 1024u + kp * 16 + tig;
        uint4 v;
        v.x = f2tf32(s[0]);
        v.y = f2tf32(s[4]);
        v.z = f2tf32(s[8]);
        v.w = f2tf32(s[12]);
        *reinterpret_cast<uint4*>(out + (size_t)q * 4) = v;
    }
}

// ---- X convert: A-block layout (unchanged, verified R7-R10) ----
__global__ void convert_X(const float* __restrict__ x, uint32_t* __restrict__ out)
{
    const int nquads = 1024 * 1024 / 4;
    for (int q = blockIdx.x * blockDim.x + threadIdx.x; q < nquads;
         q += gridDim.x * blockDim.x) {
        uint32_t blk  = (uint32_t)q >> 5;
        uint32_t lane = (uint32_t)q & 31;
        uint32_t rb = blk >> 7, kb = blk & 127u;
        uint32_t g = lane >> 2, tig = lane & 3;
        const float* s0 = x + (size_t)(rb * 16 + g) * 1024u + kb * 8 + tig;
        uint4 v;
        v.x = f2tf32(s0[0]);
        v.y = f2tf32(s0[8192]);
        v.z = f2tf32(s0[4]);
        v.w = f2tf32(s0[8192 + 4]);
        *reinterpret_cast<uint4*>(out + (size_t)q * 4) = v;
    }
}

__global__ __launch_bounds__(THREADS, 2)
void ode_step(const uint32_t* __restrict__ Atf,   // H tf32, A-block layout
              const uint32_t* __restrict__ Btf,   // W slab tf32, k16-fused layout
              const float*    __restrict__ Hfp,   // traj[n] fp32 row-major
              const float*    __restrict__ bk,
              float*          __restrict__ Hout,  // traj[n+1] fp32 row-major
              uint32_t*       __restrict__ Houttf)// next H tf32, A-block layout
{
    extern __shared__ uint32_t smem[];
    const uint32_t sbase = smem_u32(smem);

    const int tid  = threadIdx.x;
    const int wid  = tid >> 5;
    const int lane = tid & 31;
    const int g    = lane >> 2;
    const int tig  = lane & 3;
    const int wm   = wid & 1;        // 2 warp rows of 32
    const int wn   = (wid >> 1) & 1; // 2 warp cols of 32
    const int ks   = wid >> 2;       // k-split half
    const int bm   = blockIdx.y * BM;
    const int bn   = blockIdx.x * BN;
    const int rb0  = blockIdx.y * 4;  // A 16-row block base
    const int nb0  = blockIdx.x * 8;  // B 8-col block base

    auto issue_stage = [&](int s, int slot) {
        const uint32_t sst = sbase + (uint32_t)(slot * STAGE_WORDS) * 4u;
        const int kb0 = s * 8;   // k8 units (A layout)
        const int kp0 = s * 4;   // k16 units (B layout)
#pragma unroll
        for (int i = 0; i < 4; i++) {           // A: 1024 16B chunks
            int c = tid + i * THREADS;
            int rbl = c >> 8, j = c & 255;
            const uint32_t* src = Atf + ((size_t)(rb0 + rbl) * 128 + kb0) * 128 + j * 4;
            CP_ASYNC(sst + (uint32_t)(rbl * 1024 + j * 4) * 4u, src);
        }
#pragma unroll
        for (int i = 0; i < 4; i++) {           // B: 1024 16B chunks
            int c = tid + i * THREADS;
            int nbl = c >> 7, j = c & 127;      // 512 words per nb-block strip
            const uint32_t* src = Btf + ((size_t)(nb0 + nbl) * 64 + kp0) * 128 + j * 4;
            CP_ASYNC(sst + (uint32_t)(A_WORDS + nbl * 512 + j * 4) * 4u, src);
        }
        CP_COMMIT();
    };

    float acc[2][4][4];     // mt 0..1 (16 rows), nt 0..3 (8 cols)
#pragma unroll
    for (int mt = 0; mt < 2; mt++)
#pragma unroll
        for (int nt = 0; nt < 4; nt++)
#pragma unroll
            for (int r = 0; r < 4; r++) acc[mt][nt][r] = 0.0f;

    uint32_t fa[2][2][4];   // [buf][mt][a0..a3]
    uint4    fbp[2][4];     // [pair][nt] = {b0_even, b1_even, b0_odd, b1_odd}

    auto loadA = [&](const uint32_t* __restrict__ st, int j, int p) {
#pragma unroll
        for (int mt = 0; mt < 2; mt++) {
            uint4 v = *reinterpret_cast<const uint4*>(
                st + ((wm * 2 + mt) * 8 + j) * 128 + lane * 4);
            fa[p][mt][0] = v.x; fa[p][mt][1] = v.y;
            fa[p][mt][2] = v.z; fa[p][mt][3] = v.w;
        }
    };
    auto loadBpair = [&](const uint32_t* __restrict__ st, int kpl, int pr) {
#pragma unroll
        for (int nt = 0; nt < 4; nt++) {
            fbp[pr][nt] = *reinterpret_cast<const uint4*>(
                st + A_WORDS + ((wn * 4 + nt) * 4 + kpl) * 128 + lane * 4);
        }
    };
    auto do_mma = [&](int p, int pr, int odd) {
#pragma unroll
        for (int mt = 0; mt < 2; mt++)
#pragma unroll
            for (int nt = 0; nt < 4; nt++) {
                uint32_t b0 = odd ? fbp[pr][nt].z : fbp[pr][nt].x;
                uint32_t b1 = odd ? fbp[pr][nt].w : fbp[pr][nt].y;
                mma_tf32(acc[mt][nt],
                         fa[p][mt][0], fa[p][mt][1], fa[p][mt][2], fa[p][mt][3],
                         b0, b1);
            }
    };

    issue_stage(0, 0);
    issue_stage(1, 1);

    const int jb  = ks * 4;   // A k8-round base for this warp
    const int kpb = ks * 2;   // B k16-pair base for this warp
    int slot = 0, nslot = 2;
    for (int s = 0; s < KITERS; s++) {
        CP_WAIT1();          // stage s landed (s+1 may be pending)
        __syncthreads();     // stage s visible; slot for s+2 fully read

        const uint32_t* st = smem + slot * STAGE_WORDS;

        // hand-scheduled 4-round body: frag LDS first, cp.async burst behind it
        loadA(st, jb + 0, 0);
        loadBpair(st, kpb + 0, 0);

        if (s + 2 < KITERS) issue_stage(s + 2, nslot);
        else CP_COMMIT();    // keep wait_group counting exact

        loadA(st, jb + 1, 1);
        do_mma(0, 0, 0);                 // round 0
        loadA(st, jb + 2, 0);
        loadBpair(st, kpb + 1, 1);
        do_mma(1, 0, 1);                 // round 1
        loadA(st, jb + 3, 1);
        do_mma(0, 1, 0);                 // round 2
        do_mma(1, 1, 1);                 // round 3

        slot = slot + 1 == STAGES ? 0 : slot + 1;
        nslot = nslot + 1 == STAGES ? 0 : nslot + 1;
    }

    // ---- k-split reduction: exchange the nt-half each side will NOT epilogue ----
    __syncthreads();
    float* ex = reinterpret_cast<float*>(smem);
    const int p = wid & 3;          // (wm, wn) pair id, 0..3
    if (ks == 0) {
#pragma unroll
        for (int mt = 0; mt < 2; mt++)
#pragma unroll
            for (int nh = 0; nh < 2; nh++) {
                int q = mt * 2 + nh;
                float4 v = { acc[mt][2 + nh][0], acc[mt][2 + nh][1],
                             acc[mt][2 + nh][2], acc[mt][2 + nh][3] };
                *reinterpret_cast<float4*>(ex + (p * 4 + q) * 128 + lane * 4) = v;
            }
    } else {
#pragma unroll
        for (int mt = 0; mt < 2; mt++)
#pragma unroll
            for (int nh = 0; nh < 2; nh++) {
                int q = mt * 2 + nh;
                float4 v = { acc[mt][nh][0], acc[mt][nh][1],
                             acc[mt][nh][2], acc[mt][nh][3] };
                *reinterpret_cast<float4*>(ex + 2048 + (p * 4 + q) * 128 + lane * 4) = v;
            }
    }
    __syncthreads();
    const int ntb = ks ? 2 : 0;     // nt range this warp epilogues
    const int exo = ks ? 0 : 2048;  // partner's region
#pragma unroll
    for (int mt = 0; mt < 2; mt++)
#pragma unroll
        for (int nh = 0; nh < 2; nh++) {
            int q = mt * 2 + nh;
            float4 v = *reinterpret_cast<const float4*>(
                ex + exo + (p * 4 + q) * 128 + lane * 4);
            acc[mt][ntb + nh][0] += v.x;
            acc[mt][ntb + nh][1] += v.y;
            acc[mt][ntb + nh][2] += v.z;
            acc[mt][ntb + nh][3] += v.w;
        }

    // ---- fused epilogue over this warp's half (nt = ntb..ntb+1) ----
#pragma unroll
    for (int mt = 0; mt < 2; mt++) {
#pragma unroll
        for (int nh = 0; nh < 2; nh++) {
            const int nt = ntb + nh;
            const int R = bm + wm * 32 + mt * 16 + g;
            const int C = bn + wn * 32 + nt * 8 + tig * 2;
            const float b0 = __ldg(&bk[C]);
            const float b1 = __ldg(&bk[C + 1]);

            float2 h0 = *reinterpret_cast<const float2*>(&Hfp[(size_t)R * D_DIM + C]);
            float2 h1 = *reinterpret_cast<const float2*>(&Hfp[(size_t)(R + 8) * D_DIM + C]);
            float o0 = h0.x + 0.1f * fast_tanh(acc[mt][nt][0] + b0);
            float o1 = h0.y + 0.1f * fast_tanh(acc[mt][nt][1] + b1);
            float o2 = h1.x + 0.1f * fast_tanh(acc[mt][nt][2] + b0);
            float o3 = h1.y + 0.1f * fast_tanh(acc[mt][nt][3] + b1);
            *reinterpret_cast<float2*>(&Hout[(size_t)R * D_DIM + C]) = make_float2(o0, o1);
            *reinterpret_cast<float2*>(&Hout[(size_t)(R + 8) * D_DIM + C]) = make_float2(o2, o3);

            // scatter tf32 into next-step A-block layout (verified R7-R10)
            const int rb = R >> 4, kb = C >> 3;
            const int t2 = tig * 2;
            const int kw = t2 >> 2;
            const int lane0 = g * 4 + (t2 & 3);
            const int lane1 = g * 4 + ((t2 + 1) & 3);
            uint32_t* base = Houttf + ((size_t)rb * 128 + kb) * 128 + 2 * kw;
            uint2 u02 = { f2tf32(o0), f2tf32(o2) };
            uint2 u13 = { f2tf32(o1), f2tf32(o3) };
            *reinterpret_cast<uint2*>(base + lane0 * 4) = u02;
            *reinterpret_cast<uint2*>(base + lane1 * 4) = u13;
        }
    }
}

extern "C" void kernel_launch(void* const* d_in, const int* in_sizes, int n_in,
                              void* d_out, int out_size)
{
    (void)in_sizes; (void)n_in; (void)out_size;
    const float* x = (const float*)d_in[0];   // [1024, 1024]
    const float* W = (const float*)d_in[1];   // [10, 1024, 1024]
    const float* b = (const float*)d_in[2];   // [10, 1024]

    float* out  = (float*)d_out;
    const size_t BD = (size_t)D_DIM * D_DIM;
    float* feat = out;
    float* traj = out + BD;

    uint32_t *wtf = nullptr, *htf = nullptr;
    cudaGetSymbolAddress((void**)&wtf, g_Wtf);
    cudaGetSymbolAddress((void**)&htf, g_Htf);
    uint32_t* htf0 = htf;
    uint32_t* htf1 = htf + BD;

    cudaFuncSetAttribute(ode_step,
                         cudaFuncAttributeMaxDynamicSharedMemorySize, SMEM_BYTES);

    convert_W<<<4096, 256>>>(W, wtf);
    convert_X<<<1024, 256>>>(x, htf0);
    cudaMemcpyAsync(traj, x, BD * sizeof(float), cudaMemcpyDeviceToDevice, 0);

    dim3 grid(D_DIM / BN, D_DIM / BM);   // (16, 16) = 256 CTAs
    dim3 block(THREADS);

    for (int n = 0; n < 100; n++) {
        int k = n / 10;
        uint32_t* hin  = (n & 1) ? htf1 : htf0;
        uint32_t* hnew = (n & 1) ? htf0 : htf1;
        ode_step<<<grid, block, SMEM_BYTES, 0>>>(
            hin,
            wtf + (size_t)k * BD,
            traj + (size_t)n * BD,
            b + (size_t)k * D_DIM,
            traj + (size_t)(n + 1) * BD,
            hnew);
    }

    cudaMemcpyAsync(feat, traj + (size_t)100 * BD, BD * sizeof(float),
                    cudaMemcpyDeviceToDevice, 0);
}